// round 7
// baseline (speedup 1.0000x reference)
#include <cuda_runtime.h>
#include <cstdint>
#include <math.h>

#define LSTMN 256
#define CLSZ  16
#define NTH   256
#define NBLK  6

struct __align__(16) Smem {
    float wih[64 * 256];   // 64 KB: gate rows (gate q, elems [16r,16r+16)) — used for gx computes
    float whh[64 * 256];   // 64 KB: gate rows — used every cell
    float w1r[16 * 256];   // 16 KB: w1 ROWS [16r, 16r+16)
    float w2r[16 * 256];   // 16 KB: w2 ROWS [16r, 16r+16)
    float h[256];          // replicated h (broadcast each cell)
    float gxc[6][64];      // gx cache: slot 0=enc0, 1=zero(anchors 0/1), 2..5=anchors
    float g[64], bsum[64];
    float hseg[16], c16[16], w2h16[16], v16[16];
    float aw1l[6][16];     // local rows of anchors_w1
    float red2[6 * 16];    // logit partials [layer][src cta]
    float gum[8];
    float lp, ent;
    int   idx;
};

__device__ float g_lp[NBLK];
__device__ float g_ent[NBLK];
__device__ int   g_count;

// ---------------- low-level helpers ----------------

__device__ __forceinline__ uint32_t sm_u32(const void* p) {
    return (uint32_t)__cvta_generic_to_shared(p);
}
__device__ __forceinline__ uint32_t ctarank() {
    uint32_t r; asm("mov.u32 %0, %%cluster_ctarank;" : "=r"(r)); return r;
}
__device__ __forceinline__ void ds_st(uint32_t laddr, uint32_t rank, float val) {
    uint32_t ra;
    asm volatile("mapa.shared::cluster.u32 %0, %1, %2;" : "=r"(ra) : "r"(laddr), "r"(rank));
    asm volatile("st.shared::cluster.f32 [%0], %1;" :: "r"(ra), "f"(val) : "memory");
}
__device__ __forceinline__ void csync() {
    asm volatile("barrier.cluster.arrive.aligned;" ::: "memory");
    asm volatile("barrier.cluster.wait.aligned;" ::: "memory");
}

// threefry2x32, 20 rounds — exact JAX semantics
__device__ __forceinline__ uint2 tf2x32(uint2 key, uint2 ctr) {
    uint32_t ks0 = key.x, ks1 = key.y, ks2 = ks0 ^ ks1 ^ 0x1BD11BDAu;
    uint32_t x0 = ctr.x + ks0, x1 = ctr.y + ks1;
#define TF_RND(r) { x0 += x1; x1 = (x1 << (r)) | (x1 >> (32 - (r))); x1 ^= x0; }
    TF_RND(13) TF_RND(15) TF_RND(26) TF_RND(6)  x0 += ks1; x1 += ks2 + 1u;
    TF_RND(17) TF_RND(29) TF_RND(16) TF_RND(24) x0 += ks2; x1 += ks0 + 2u;
    TF_RND(13) TF_RND(15) TF_RND(26) TF_RND(6)  x0 += ks0; x1 += ks1 + 3u;
    TF_RND(17) TF_RND(29) TF_RND(16) TF_RND(24) x0 += ks1; x1 += ks2 + 4u;
    TF_RND(13) TF_RND(15) TF_RND(26) TF_RND(6)  x0 += ks2; x1 += ks0 + 5u;
#undef TF_RND
    return make_uint2(x0, x1);
}

// fast tanh/sigmoid on MUFU.EX2 path (hot loops; err ~1e-6, tolerance 1e-3)
__device__ __forceinline__ float my_tanh(float xv) {
    float ax = fabsf(xv);
    float t = __expf(-2.0f * ax);
    float r = (1.0f - t) / (1.0f + t);
    return copysignf(r, xv);
}
__device__ __forceinline__ float my_sig(float xv) {
    return 1.0f / (1.0f + __expf(-xv));
}

// 64-row matvec: dst[r] = W[r,:] @ hv   (8 warps x 8 rows, conflict-free)
__device__ __forceinline__ void mv64(const float* W, const float* hv, float* dst, int tid) {
    const int lane = tid & 31, wrp = tid >> 5;
    const float4* HV = (const float4*)hv;
    float4 ha = HV[lane], hb = HV[lane + 32];
#pragma unroll
    for (int rr = 0; rr < 8; rr++) {
        int r = wrp * 8 + rr;
        const float4* wh = (const float4*)(W + r * LSTMN);
        float4 a = wh[lane], b4 = wh[lane + 32];
        float acc = a.x * ha.x + a.y * ha.y + a.z * ha.z + a.w * ha.w
                  + b4.x * hb.x + b4.y * hb.y + b4.z * hb.z + b4.w * hb.w;
        acc += __shfl_xor_sync(0xffffffffu, acc, 16);
        acc += __shfl_xor_sync(0xffffffffu, acc, 8);
        acc += __shfl_xor_sync(0xffffffffu, acc, 4);
        acc += __shfl_xor_sync(0xffffffffu, acc, 2);
        acc += __shfl_xor_sync(0xffffffffu, acc, 1);
        if (lane == 0) dst[r] = acc;
    }
}

// 16-row matvec: dst[row] = W[row,:] @ hv   (16 lanes per row, width-16 reduce)
__device__ __forceinline__ void mv16(const float* W, const float* hv, float* dst, int tid) {
    int row = tid >> 4, seg = tid & 15;
    const float4* wr = (const float4*)(W + row * LSTMN + seg * 16);
    const float4* hp = (const float4*)(hv + seg * 16);
    float acc = 0.0f;
#pragma unroll
    for (int k = 0; k < 4; k++) {
        float4 w4 = wr[k], h4 = hp[k];
        acc += w4.x * h4.x + w4.y * h4.y + w4.z * h4.z + w4.w * h4.w;
    }
    acc += __shfl_xor_sync(0xffffffffu, acc, 8);
    acc += __shfl_xor_sync(0xffffffffu, acc, 4);
    acc += __shfl_xor_sync(0xffffffffu, acc, 2);
    acc += __shfl_xor_sync(0xffffffffu, acc, 1);
    if (seg == 0) dst[row] = acc;
}

// ---------------- one LSTM cell ----------------
// g = gxc[xs] + whh @ h + bsum; local H; optional h broadcast + csync
__device__ __forceinline__ void do_cell(Smem* s, int rank, int tid, int xs,
                                        bool hzero, bool bcast) {
    __syncthreads();
    if (hzero) {
        if (tid < 64) s->g[tid] = s->gxc[xs][tid] + s->bsum[tid];
    } else {
        const int lane = tid & 31, wrp = tid >> 5;
        const float4* HV = (const float4*)s->h;
        float4 ha = HV[lane], hb = HV[lane + 32];
#pragma unroll
        for (int rr = 0; rr < 8; rr++) {
            int r = wrp * 8 + rr;
            const float4* wh = (const float4*)(s->whh + r * LSTMN);
            float4 a = wh[lane], b4 = wh[lane + 32];
            float acc = a.x * ha.x + a.y * ha.y + a.z * ha.z + a.w * ha.w
                      + b4.x * hb.x + b4.y * hb.y + b4.z * hb.z + b4.w * hb.w;
            acc += __shfl_xor_sync(0xffffffffu, acc, 16);
            acc += __shfl_xor_sync(0xffffffffu, acc, 8);
            acc += __shfl_xor_sync(0xffffffffu, acc, 4);
            acc += __shfl_xor_sync(0xffffffffu, acc, 2);
            acc += __shfl_xor_sync(0xffffffffu, acc, 1);
            if (lane == 0) s->g[r] = acc + s->gxc[xs][r] + s->bsum[r];
        }
    }
    __syncthreads();
    if (tid < 16) {
        int j = tid;
        float gi = s->g[j], gf = s->g[16 + j], gg = s->g[32 + j], go = s->g[48 + j];
        float cn = my_sig(gf) * s->c16[j] + my_sig(gi) * my_tanh(gg);
        float hn = my_sig(go) * my_tanh(cn);
        s->c16[j] = cn;
        s->hseg[j] = hn;
        if (bcast) {
            uint32_t ha = sm_u32(&s->h[rank * 16 + j]);
#pragma unroll
            for (int r = 0; r < CLSZ; r++) ds_st(ha, (uint32_t)r, hn);
        }
    }
    if (bcast) csync(); else __syncthreads();
}

// after anchor csync: local aw1 rows + gx cache for this anchor (all CTAs, balanced)
__device__ __forceinline__ void anchor_post(Smem* s, int tid, int slot) {
    mv16(s->w1r, s->h, s->aw1l[slot], tid);
    mv64(s->wih, s->h, s->gxc[slot], tid);
}

// ---------------- sampling (post csync-A; fully balanced) ----------------
__device__ __forceinline__ void do_sample(Smem* s, int rank, int tid, int layer,
                                          uint2 bkey, int step, float* out, int b) {
    // own-row w2h from full (just-published) h — local, no gather
    mv16(s->w2r, s->h, s->w2h16, tid);
    // warp 7: Gumbel precompute (independent of logits)
    if ((tid >> 5) == 7) {
        int lane = tid & 31;
        if (lane < layer) {
            uint2 skey = tf2x32(bkey, make_uint2(0u, (uint32_t)step));
            uint2 o = tf2x32(skey, make_uint2(0u, (uint32_t)lane));
            uint32_t bits = o.x ^ o.y;
            float u = __uint_as_float((bits >> 9) | 0x3f800000u) - 1.0f;
            const float TINYF = 1.17549435e-38f;
            float up = fmaxf(TINYF, u + TINYF);
            s->gum[lane] = -logf(-logf(up));
        }
    }
    __syncthreads();
    // balanced qv partials: thread (l,j) handles layer l, own elem j
    {
        int l = tid >> 4, j = tid & 15;
        float val = 0.0f;
        if (l < layer)   // l in [0,6) only for tid<96; others contribute 0
            val = my_tanh(s->aw1l[l][j] + s->w2h16[j]) * s->v16[j];
        val += __shfl_xor_sync(0xffffffffu, val, 8);
        val += __shfl_xor_sync(0xffffffffu, val, 4);
        val += __shfl_xor_sync(0xffffffffu, val, 2);
        val += __shfl_xor_sync(0xffffffffu, val, 1);
        if (j == 0 && l < layer) {
            uint32_t ra = sm_u32(&s->red2[l * 16 + rank]);
#pragma unroll
            for (int r = 0; r < CLSZ; r++) ds_st(ra, (uint32_t)r, val);
        }
    }
    csync();   // logit partials visible everywhere

    if (tid < 32) {
        const int lane = tid;
        const bool act = lane < layer;
        float logit = 0.0f;
        if (act) {
            float sum = 0.0f;
#pragma unroll
            for (int r = 0; r < CLSZ; r++) sum += s->red2[lane * 16 + r];
            logit = 1.1f * my_tanh(sum * 0.2f);
        }
        float pert = act ? (s->gum[lane] + logit) : -1e38f;
        float bp = pert; int bi = act ? lane : 64;
#pragma unroll
        for (int off = 16; off; off >>= 1) {
            float op = __shfl_xor_sync(0xffffffffu, bp, off);
            int oi = __shfl_xor_sync(0xffffffffu, bi, off);
            if (op > bp || (op == bp && oi < bi)) { bp = op; bi = oi; }
        }
        float lm = act ? logit : -1e38f;
#pragma unroll
        for (int off = 16; off; off >>= 1)
            lm = fmaxf(lm, __shfl_xor_sync(0xffffffffu, lm, off));
        float se = act ? expf(logit - lm) : 0.0f;
#pragma unroll
        for (int off = 16; off; off >>= 1)
            se += __shfl_xor_sync(0xffffffffu, se, off);
        float lse = logf(se);
        float ls = logit - lm - lse;
        float ls_best = __shfl_sync(0xffffffffu, ls, bi);
        float ec = act ? (-ls * expf(ls)) : 0.0f;
#pragma unroll
        for (int off = 16; off; off >>= 1)
            ec += __shfl_xor_sync(0xffffffffu, ec, off);
        if (lane == 0) {
            s->lp += -ls_best;
            s->ent += ec;
            s->idx = bi;
            if (rank == 0) out[b * 10 + step] = (float)bi;
        }
    }
    __syncthreads();
}

// ---------------- main kernel: one 16-CTA cluster per block ----------------
__global__ void __launch_bounds__(NTH, 1) ctrl_kernel(
    const float* __restrict__ enc_w, const float* __restrict__ w_ih,
    const float* __restrict__ w_hh, const float* __restrict__ b_ih,
    const float* __restrict__ b_hh, const float* __restrict__ w1,
    const float* __restrict__ w2, const float* __restrict__ v,
    float* __restrict__ out)
{
    extern __shared__ char smraw[];
    Smem* s = (Smem*)smraw;
    const int tid = threadIdx.x;
    const int rank = (int)ctarank();
    const int b = blockIdx.y;

    // ---- prologue ----
    {
        // gate rows: local row lr -> global row (lr/16)*256 + rank*16 + lr%16
        for (int i = tid; i < 64 * 64; i += NTH) {
            int lr = i >> 6, pos = i & 63;
            int grow = ((lr >> 4) << 8) + rank * 16 + (lr & 15);
            ((float4*)s->wih)[i] = ((const float4*)w_ih)[grow * 64 + pos];
        }
        for (int i = tid; i < 64 * 64; i += NTH) {
            int lr = i >> 6, pos = i & 63;
            int grow = ((lr >> 4) << 8) + rank * 16 + (lr & 15);
            ((float4*)s->whh)[i] = ((const float4*)w_hh)[grow * 64 + pos];
        }
        // w1 / w2 ROWS [rank*16, rank*16+16)
        for (int i = tid; i < 16 * 64; i += NTH) {
            int row = i >> 6, pos = i & 63;
            ((float4*)s->w1r)[i] = ((const float4*)w1)[(rank * 16 + row) * 64 + pos];
            ((float4*)s->w2r)[i] = ((const float4*)w2)[(rank * 16 + row) * 64 + pos];
        }
        if (tid < 64) {
            int grow = ((tid >> 4) << 8) + rank * 16 + (tid & 15);
            s->bsum[tid] = b_ih[grow] + b_hh[grow];
            s->gxc[1][tid] = 0.0f;   // anchors 0/1 are zero vectors
        }
        if (tid < 16) { s->v16[tid] = v[rank * 16 + tid]; s->c16[tid] = 0.0f; }
        s->h[tid] = enc_w[tid];      // temp: enc0 as matvec input
        if (tid == 0) { s->lp = 0.0f; s->ent = 0.0f; s->idx = 0; }
    }
    __syncthreads();
    mv64(s->wih, s->h, s->gxc[0], tid);   // gx(enc0), reused by 6 cells
    __syncthreads();

    const uint2 key42 = make_uint2(0u, 42u);
    const uint2 bkey = tf2x32(key42, make_uint2(0u, (uint32_t)b));

    // first two reference layers = one identical zero-state cell (h=0 -> skip whh)
    do_cell(s, rank, tid, 0, true, true);
    mv16(s->w1r, s->h, s->aw1l[0], tid);
    __syncthreads();
    if (tid < 16) s->aw1l[1][tid] = s->aw1l[0][tid];

    int step = 0;
    int xslot = 0;   // inputs = enc0 entering layer 2
#pragma unroll 1
    for (int layer = 2; layer <= 6; layer++) {
#pragma unroll 1
        for (int rep = 0; rep < 2; rep++) {
            do_cell(s, rank, tid, xslot, false, true);
            do_sample(s, rank, tid, layer, bkey, step, out, b);
            step++;
            xslot = (s->idx < 2) ? 1 : s->idx;   // anchors 0/1 are zero -> slot 1
        }
        if (layer < 6) {
            do_cell(s, rank, tid, xslot, false, true);   // anchor cell
            anchor_post(s, tid, layer);
            xslot = 0;                                   // inputs = enc0
        } else {
            do_cell(s, rank, tid, xslot, false, false);  // final cell, local only
        }
    }

    // ---- epilogue: deadlock-free last-cluster scalar reduction ----
    if (rank == 0 && tid == 0) {
        g_lp[b] = s->lp;
        g_ent[b] = s->ent;
        __threadfence();
        int prev = atomicAdd(&g_count, 1);
        if (prev == NBLK - 1) {
            __threadfence();
            float slp = 0.0f, sent = 0.0f;
#pragma unroll
            for (int bb = 0; bb < NBLK; bb++) {
                slp += ((volatile float*)g_lp)[bb];
                sent += ((volatile float*)g_ent)[bb];
            }
            out[60] = slp;
            out[61] = sent;
            g_count = 0;   // reset for graph replay
        }
    }
    if (b == NBLK - 1 && tid < 16) {
        out[62 + rank * 16 + tid] = s->c16[tid];
        out[62 + 256 + rank * 16 + tid] = s->hseg[tid];
    }
}

extern "C" void kernel_launch(void* const* d_in, const int* in_sizes, int n_in,
                              void* d_out, int out_size) {
    const float* enc_w = (const float*)d_in[0];
    const float* w_ih  = (const float*)d_in[1];
    const float* w_hh  = (const float*)d_in[2];
    const float* b_ih  = (const float*)d_in[3];
    const float* b_hh  = (const float*)d_in[4];
    const float* w1    = (const float*)d_in[5];
    const float* w2    = (const float*)d_in[6];
    const float* v     = (const float*)d_in[7];
    float* out = (float*)d_out;

    cudaFuncSetAttribute(ctrl_kernel,
                         cudaFuncAttributeMaxDynamicSharedMemorySize,
                         (int)sizeof(Smem));
    cudaFuncSetAttribute(ctrl_kernel,
                         cudaFuncAttributeNonPortableClusterSizeAllowed, 1);

    cudaLaunchConfig_t cfg = {};
    cfg.gridDim = dim3(CLSZ, NBLK, 1);
    cfg.blockDim = dim3(NTH, 1, 1);
    cfg.dynamicSmemBytes = sizeof(Smem);
    cfg.stream = 0;
    cudaLaunchAttribute at[1];
    at[0].id = cudaLaunchAttributeClusterDimension;
    at[0].val.clusterDim.x = CLSZ;
    at[0].val.clusterDim.y = 1;
    at[0].val.clusterDim.z = 1;
    cfg.attrs = at;
    cfg.numAttrs = 1;

    cudaLaunchKernelEx(&cfg, ctrl_kernel,
                       enc_w, w_ih, w_hh, b_ih, b_hh, w1, w2, v, out);
}

// round 9
// speedup vs baseline: 1.0058x; 1.0058x over previous
#include <cuda_runtime.h>
#include <cstdint>
#include <math.h>

#define LSTMN 256
#define CLSZ  16
#define NTH   256
#define NBLK  6

struct __align__(16) Smem {
    float wih[64 * 256];   // 64 KB: gate rows (gate q, elems [16r,16r+16)) — gx computes
    float whh[64 * 256];   // 64 KB: gate rows — every cell
    float w1r[16 * 256];   // 16 KB: w1 ROWS [16r,16r+16)
    float w2r[16 * 256];   // 16 KB: w2 ROWS
    float h[2][256];       // double-buffered replicated h
    float gxc[6][64];      // gx cache: 0=enc0, 1=zero(anchors 0/1), 2..5=anchors
    float gtmp[64];        // whh @ h partial gates
    float bsum[64];
    float hseg[16], c16[16], w2h16[16], v16[16];
    float aw1l[6][16];     // local rows of anchors_w1
    float red2[6 * 16];    // logit partials [layer][src cta]
    float gum[8];
    float lp, ent;
    int   idx;
    unsigned long long mbar;   // round barrier (count = 16)
};

__device__ float g_lp[NBLK];
__device__ float g_ent[NBLK];
__device__ int   g_count;

// ---------------- low-level helpers ----------------

__device__ __forceinline__ uint32_t sm_u32(const void* p) {
    return (uint32_t)__cvta_generic_to_shared(p);
}
__device__ __forceinline__ uint32_t ctarank() {
    uint32_t r; asm("mov.u32 %0, %%cluster_ctarank;" : "=r"(r)); return r;
}
__device__ __forceinline__ void ds_st(uint32_t laddr, uint32_t rank, float val) {
    uint32_t ra;
    asm volatile("mapa.shared::cluster.u32 %0, %1, %2;" : "=r"(ra) : "r"(laddr), "r"(rank));
    asm volatile("st.shared::cluster.f32 [%0], %1;" :: "r"(ra), "f"(val) : "memory");
}

// ---- lightweight all-to-all round via mbarrier (replaces cluster.sync) ----
__device__ __forceinline__ void round_arrive(Smem* s, int tid) {
    asm volatile("fence.acq_rel.cluster;" ::: "memory");
    __syncthreads();
    if (tid == 0) {
        uint32_t la = sm_u32(&s->mbar);
#pragma unroll
        for (int r = 0; r < CLSZ; r++) {
            uint32_t ra;
            asm volatile("mapa.shared::cluster.u32 %0, %1, %2;"
                         : "=r"(ra) : "r"(la), "r"(r));
            asm volatile("mbarrier.arrive.shared::cluster.b64 _, [%0];"
                         :: "r"(ra) : "memory");
        }
    }
}
__device__ __forceinline__ void round_wait(Smem* s, int k) {
    uint32_t la = sm_u32(&s->mbar);
    uint32_t par = (uint32_t)(k & 1);
    uint32_t done;
    asm volatile(
        "{\n\t.reg .pred p;\n\t"
        "mbarrier.try_wait.parity.acquire.cluster.shared::cta.b64 p, [%1], %2;\n\t"
        "selp.b32 %0, 1, 0, p;\n\t}"
        : "=r"(done) : "r"(la), "r"(par) : "memory");
    if (!done) {
        asm volatile(
            "{\n\t.reg .pred P1;\n\t"
            "W%=:\n\t"
            "mbarrier.try_wait.parity.acquire.cluster.shared::cta.b64 P1, [%0], %1, 0x989680;\n\t"
            "@P1 bra D%=;\n\t"
            "bra W%=;\n\t"
            "D%=:\n\t}"
            :: "r"(la), "r"(par) : "memory");
    }
}

// threefry2x32, 20 rounds — exact JAX semantics
__device__ __forceinline__ uint2 tf2x32(uint2 key, uint2 ctr) {
    uint32_t ks0 = key.x, ks1 = key.y, ks2 = ks0 ^ ks1 ^ 0x1BD11BDAu;
    uint32_t x0 = ctr.x + ks0, x1 = ctr.y + ks1;
#define TF_RND(r) { x0 += x1; x1 = (x1 << (r)) | (x1 >> (32 - (r))); x1 ^= x0; }
    TF_RND(13) TF_RND(15) TF_RND(26) TF_RND(6)  x0 += ks1; x1 += ks2 + 1u;
    TF_RND(17) TF_RND(29) TF_RND(16) TF_RND(24) x0 += ks2; x1 += ks0 + 2u;
    TF_RND(13) TF_RND(15) TF_RND(26) TF_RND(6)  x0 += ks0; x1 += ks1 + 3u;
    TF_RND(17) TF_RND(29) TF_RND(16) TF_RND(24) x0 += ks1; x1 += ks2 + 4u;
    TF_RND(13) TF_RND(15) TF_RND(26) TF_RND(6)  x0 += ks2; x1 += ks0 + 5u;
#undef TF_RND
    return make_uint2(x0, x1);
}

__device__ __forceinline__ float my_tanh(float xv) {
    float ax = fabsf(xv);
    float t = __expf(-2.0f * ax);
    float r = (1.0f - t) / (1.0f + t);
    return copysignf(r, xv);
}
__device__ __forceinline__ float my_sig(float xv) {
    return 1.0f / (1.0f + __expf(-xv));
}

// 64-row matvec: dst[r] = W[r,:] @ hv
__device__ __forceinline__ void mv64(const float* W, const float* hv, float* dst, int tid) {
    const int lane = tid & 31, wrp = tid >> 5;
    const float4* HV = (const float4*)hv;
    float4 ha = HV[lane], hb = HV[lane + 32];
#pragma unroll
    for (int rr = 0; rr < 8; rr++) {
        int r = wrp * 8 + rr;
        const float4* wh = (const float4*)(W + r * LSTMN);
        float4 a = wh[lane], b4 = wh[lane + 32];
        float acc = a.x * ha.x + a.y * ha.y + a.z * ha.z + a.w * ha.w
                  + b4.x * hb.x + b4.y * hb.y + b4.z * hb.z + b4.w * hb.w;
        acc += __shfl_xor_sync(0xffffffffu, acc, 16);
        acc += __shfl_xor_sync(0xffffffffu, acc, 8);
        acc += __shfl_xor_sync(0xffffffffu, acc, 4);
        acc += __shfl_xor_sync(0xffffffffu, acc, 2);
        acc += __shfl_xor_sync(0xffffffffu, acc, 1);
        if (lane == 0) dst[r] = acc;
    }
}

// 16-row matvec: dst[row] = W[row,:] @ hv
__device__ __forceinline__ void mv16(const float* W, const float* hv, float* dst, int tid) {
    int row = tid >> 4, seg = tid & 15;
    const float4* wr = (const float4*)(W + row * LSTMN + seg * 16);
    const float4* hp = (const float4*)(hv + seg * 16);
    float acc = 0.0f;
#pragma unroll
    for (int k = 0; k < 4; k++) {
        float4 w4 = wr[k], h4 = hp[k];
        acc += w4.x * h4.x + w4.y * h4.y + w4.z * h4.z + w4.w * h4.w;
    }
    acc += __shfl_xor_sync(0xffffffffu, acc, 8);
    acc += __shfl_xor_sync(0xffffffffu, acc, 4);
    acc += __shfl_xor_sync(0xffffffffu, acc, 2);
    acc += __shfl_xor_sync(0xffffffffu, acc, 1);
    if (seg == 0) dst[row] = acc;
}

// H phase from gtmp + gxc[xs] + bsum; optional push of new h into buffer nb
__device__ __forceinline__ void h_phase(Smem* s, int rank, int tid, int xs, int nb,
                                        bool push, bool hzero) {
    if (tid < 16) {
        int j = tid;
        float gi, gf, gg, go;
        if (hzero) {
            gi = s->gxc[xs][j] + s->bsum[j];
            gf = s->gxc[xs][16 + j] + s->bsum[16 + j];
            gg = s->gxc[xs][32 + j] + s->bsum[32 + j];
            go = s->gxc[xs][48 + j] + s->bsum[48 + j];
        } else {
            gi = s->gtmp[j] + s->gxc[xs][j] + s->bsum[j];
            gf = s->gtmp[16 + j] + s->gxc[xs][16 + j] + s->bsum[16 + j];
            gg = s->gtmp[32 + j] + s->gxc[xs][32 + j] + s->bsum[32 + j];
            go = s->gtmp[48 + j] + s->gxc[xs][48 + j] + s->bsum[48 + j];
        }
        float cn = my_sig(gf) * s->c16[j] + my_sig(gi) * my_tanh(gg);
        float hn = my_sig(go) * my_tanh(cn);
        s->c16[j] = cn;
        s->hseg[j] = hn;
        if (push) {
            uint32_t ha = sm_u32(&s->h[nb][rank * 16 + j]);
#pragma unroll
            for (int r = 0; r < CLSZ; r++) ds_st(ha, (uint32_t)r, hn);
        }
    }
}

// ---------------- main kernel: one 16-CTA cluster per block ----------------
__global__ void __launch_bounds__(NTH, 1) ctrl_kernel(
    const float* __restrict__ enc_w, const float* __restrict__ w_ih,
    const float* __restrict__ w_hh, const float* __restrict__ b_ih,
    const float* __restrict__ b_hh, const float* __restrict__ w1,
    const float* __restrict__ w2, const float* __restrict__ v,
    float* __restrict__ out)
{
    extern __shared__ char smraw[];
    Smem* s = (Smem*)smraw;
    const int tid = threadIdx.x;
    const int rank = (int)ctarank();
    const int b = blockIdx.y;

    // ---- prologue ----
    {
        for (int i = tid; i < 64 * 64; i += NTH) {
            int lr = i >> 6, pos = i & 63;
            int grow = ((lr >> 4) << 8) + rank * 16 + (lr & 15);
            ((float4*)s->wih)[i] = ((const float4*)w_ih)[grow * 64 + pos];
        }
        for (int i = tid; i < 64 * 64; i += NTH) {
            int lr = i >> 6, pos = i & 63;
            int grow = ((lr >> 4) << 8) + rank * 16 + (lr & 15);
            ((float4*)s->whh)[i] = ((const float4*)w_hh)[grow * 64 + pos];
        }
        for (int i = tid; i < 16 * 64; i += NTH) {
            int row = i >> 6, pos = i & 63;
            ((float4*)s->w1r)[i] = ((const float4*)w1)[(rank * 16 + row) * 64 + pos];
            ((float4*)s->w2r)[i] = ((const float4*)w2)[(rank * 16 + row) * 64 + pos];
        }
        if (tid < 64) {
            int grow = ((tid >> 4) << 8) + rank * 16 + (tid & 15);
            s->bsum[tid] = b_ih[grow] + b_hh[grow];
            s->gxc[1][tid] = 0.0f;   // anchors 0/1 are zero vectors
        }
        if (tid < 16) { s->v16[tid] = v[rank * 16 + tid]; s->c16[tid] = 0.0f; }
        s->h[0][tid] = enc_w[tid];   // temp: enc0 as matvec input
        if (tid == 0) {
            s->lp = 0.0f; s->ent = 0.0f; s->idx = 0;
            uint32_t ma = sm_u32(&s->mbar);
            asm volatile("mbarrier.init.shared.b64 [%0], %1;" :: "r"(ma), "r"(CLSZ) : "memory");
        }
    }
    __syncthreads();
    mv64(s->wih, s->h[0], s->gxc[0], tid);   // gx(enc0), reused by all enc0 cells
    // one heavyweight sync: mbarriers + smem ready everywhere
    asm volatile("barrier.cluster.arrive.aligned;" ::: "memory");
    asm volatile("barrier.cluster.wait.aligned;" ::: "memory");

    const uint2 key42 = make_uint2(0u, 42u);
    const uint2 bkey = tf2x32(key42, make_uint2(0u, (uint32_t)b));

    int krnd = 0;   // round counter — identical on all CTAs
    int hb = 0;     // current h buffer

    // ---- Z cell (zero state, input enc0) -> h1 in h[0] ----
    __syncthreads();
    h_phase(s, rank, tid, 0, 0, true, true);
    round_arrive(s, tid);
    round_wait(s, krnd); krnd++;

    // aw1[0] = aw1[1] = w1 @ h1 ; PRIMING cell1 = cell(enc0, h1, c1) -> h[1]
    mv16(s->w1r, s->h[0], s->aw1l[0], tid);
    mv64(s->whh, s->h[0], s->gtmp, tid);
    __syncthreads();
    if (tid < 16) s->aw1l[1][tid] = s->aw1l[0][tid];
    h_phase(s, rank, tid, 0, 1, true, false);
    round_arrive(s, tid);
    round_wait(s, krnd); krnd++;
    hb = 1;

    int step = 0;
#pragma unroll 1
    for (int layer = 2; layer <= 6; layer++) {
#pragma unroll 1
        for (int rep = 0; rep < 2; rep++) {
            // ---- sample step: h[hb] = h of the cell for THIS sample ----
            mv16(s->w2r, s->h[hb], s->w2h16, tid);      // own-row w2h
            if ((tid >> 5) == 7) {                       // Gumbel precompute
                int lane = tid & 31;
                if (lane < layer) {
                    uint2 skey = tf2x32(bkey, make_uint2(0u, (uint32_t)step));
                    uint2 o = tf2x32(skey, make_uint2(0u, (uint32_t)lane));
                    uint32_t bits = o.x ^ o.y;
                    float u = __uint_as_float((bits >> 9) | 0x3f800000u) - 1.0f;
                    const float TINYF = 1.17549435e-38f;
                    float up = fmaxf(TINYF, u + TINYF);
                    s->gum[lane] = -logf(-logf(up));
                }
            }
            __syncthreads();
            {   // balanced qv partials: thread (l,j) -> layer l, own elem j
                int l = tid >> 4, j = tid & 15;
                float val = 0.0f;
                if (l < layer)
                    val = my_tanh(s->aw1l[l][j] + s->w2h16[j]) * s->v16[j];
                val += __shfl_xor_sync(0xffffffffu, val, 8);
                val += __shfl_xor_sync(0xffffffffu, val, 4);
                val += __shfl_xor_sync(0xffffffffu, val, 2);
                val += __shfl_xor_sync(0xffffffffu, val, 1);
                if (j == 0 && l < layer) {
                    uint32_t ra = sm_u32(&s->red2[l * 16 + rank]);
#pragma unroll
                    for (int r = 0; r < CLSZ; r++) ds_st(ra, (uint32_t)r, val);
                }
            }
            round_arrive(s, tid);                 // B round posted
            mv64(s->whh, s->h[hb], s->gtmp, tid); // overlap: next cell's whh @ h
            round_wait(s, krnd); krnd++;

            // ---- logits + Gumbel argmax (warp 0, replicated per CTA) ----
            if (tid < 32) {
                const int lane = tid;
                const bool act = lane < layer;
                float logit = 0.0f;
                if (act) {
                    float sum = 0.0f;
#pragma unroll
                    for (int r = 0; r < CLSZ; r++) sum += s->red2[lane * 16 + r];
                    logit = 1.1f * my_tanh(sum * 0.2f);
                }
                float pert = act ? (s->gum[lane] + logit) : -1e38f;
                float bp = pert; int bi = act ? lane : 64;
#pragma unroll
                for (int off = 16; off; off >>= 1) {
                    float op = __shfl_xor_sync(0xffffffffu, bp, off);
                    int oi = __shfl_xor_sync(0xffffffffu, bi, off);
                    if (op > bp || (op == bp && oi < bi)) { bp = op; bi = oi; }
                }
                float lm = act ? logit : -1e38f;
#pragma unroll
                for (int off = 16; off; off >>= 1)
                    lm = fmaxf(lm, __shfl_xor_sync(0xffffffffu, lm, off));
                float se = act ? expf(logit - lm) : 0.0f;
#pragma unroll
                for (int off = 16; off; off >>= 1)
                    se += __shfl_xor_sync(0xffffffffu, se, off);
                float lse = logf(se);
                float ls = logit - lm - lse;
                float ls_best = __shfl_sync(0xffffffffu, ls, bi);
                float ec = act ? (-ls * expf(ls)) : 0.0f;
#pragma unroll
                for (int off = 16; off; off >>= 1)
                    ec += __shfl_xor_sync(0xffffffffu, ec, off);
                if (lane == 0) {
                    s->lp += -ls_best;
                    s->ent += ec;
                    s->idx = bi;
                    if (rank == 0) out[b * 10 + step] = (float)bi;
                }
            }
            __syncthreads();   // idx + gtmp visible
            step++;
            int xslot = (s->idx < 2) ? 1 : s->idx;

            // ---- next cell: H phase with gxc[xslot] ----
            // rep==1 -> this IS the layer's anchor cell (input anc[idx])
            bool last_cell = (layer == 6 && rep == 1);
            if (!last_cell) {
                h_phase(s, rank, tid, xslot, hb ^ 1, true, false);
                round_arrive(s, tid);
                round_wait(s, krnd); krnd++;
                hb ^= 1;
            } else {
                h_phase(s, rank, tid, xslot, 0, false, false);  // final anchor, local
            }
        }
        if (layer < 6) {
            // ---- anchor bookkeeping on h[hb] (= anchor h) + next layer's cell1 ----
            mv16(s->w1r, s->h[hb], s->aw1l[layer], tid);   // aw1[layer]
            mv64(s->wih, s->h[hb], s->gxc[layer], tid);    // gx cache of this anchor
            mv64(s->whh, s->h[hb], s->gtmp, tid);          // recurrent part of cell1'
            __syncthreads();
            h_phase(s, rank, tid, 0, hb ^ 1, true, false); // cell1' = cell(enc0, anchor)
            round_arrive(s, tid);
            round_wait(s, krnd); krnd++;
            hb ^= 1;
        }
    }

    // ---- epilogue: deadlock-free last-cluster scalar reduction ----
    if (rank == 0 && tid == 0) {
        g_lp[b] = s->lp;
        g_ent[b] = s->ent;
        __threadfence();
        int prev = atomicAdd(&g_count, 1);
        if (prev == NBLK - 1) {
            __threadfence();
            float slp = 0.0f, sent = 0.0f;
#pragma unroll
            for (int bb = 0; bb < NBLK; bb++) {
                slp += ((volatile float*)g_lp)[bb];
                sent += ((volatile float*)g_ent)[bb];
            }
            out[60] = slp;
            out[61] = sent;
            g_count = 0;   // reset for graph replay
        }
    }
    __syncthreads();
    if (b == NBLK - 1 && tid < 16) {
        out[62 + rank * 16 + tid] = s->c16[tid];
        out[62 + 256 + rank * 16 + tid] = s->hseg[tid];
    }
}

extern "C" void kernel_launch(void* const* d_in, const int* in_sizes, int n_in,
                              void* d_out, int out_size) {
    const float* enc_w = (const float*)d_in[0];
    const float* w_ih  = (const float*)d_in[1];
    const float* w_hh  = (const float*)d_in[2];
    const float* b_ih  = (const float*)d_in[3];
    const float* b_hh  = (const float*)d_in[4];
    const float* w1    = (const float*)d_in[5];
    const float* w2    = (const float*)d_in[6];
    const float* v     = (const float*)d_in[7];
    float* out = (float*)d_out;

    cudaFuncSetAttribute(ctrl_kernel,
                         cudaFuncAttributeMaxDynamicSharedMemorySize,
                         (int)sizeof(Smem));
    cudaFuncSetAttribute(ctrl_kernel,
                         cudaFuncAttributeNonPortableClusterSizeAllowed, 1);

    cudaLaunchConfig_t cfg = {};
    cfg.gridDim = dim3(CLSZ, NBLK, 1);
    cfg.blockDim = dim3(NTH, 1, 1);
    cfg.dynamicSmemBytes = sizeof(Smem);
    cfg.stream = 0;
    cudaLaunchAttribute at[1];
    at[0].id = cudaLaunchAttributeClusterDimension;
    at[0].val.clusterDim.x = CLSZ;
    at[0].val.clusterDim.y = 1;
    at[0].val.clusterDim.z = 1;
    cfg.attrs = at;
    cfg.numAttrs = 1;

    cudaLaunchKernelEx(&cfg, ctrl_kernel,
                       enc_w, w_ih, w_hh, b_ih, b_hh, w1, w2, v, out);
}